// round 3
// baseline (speedup 1.0000x reference)
#include <cuda_runtime.h>

#define NSIZE   1024
#define NINPUT  1024
#define NCTX    512
#define NBATCH  256
#define NBUCKET 16
#define SB      8          // neurons per CTA

static __device__ float g_logT[NBATCH * NINPUT];        // logits transposed: [b][i]
static __device__ unsigned char g_idx[NSIZE * NBATCH];  // bucket index per (s, b)

typedef unsigned long long u64;

__device__ __forceinline__ u64 ffma2(u64 a, u64 b, u64 c) {
    u64 d;
    asm("fma.rn.f32x2 %0, %1, %2, %3;" : "=l"(d) : "l"(a), "l"(b), "l"(c));
    return d;
}
__device__ __forceinline__ float2 unpack2(u64 v) {
    float2 r;
    asm("mov.b64 {%0, %1}, %2;" : "=f"(r.x), "=f"(r.y) : "l"(v));
    return r;
}
__device__ __forceinline__ u64 pack2(float lo, float hi) {
    u64 r;
    asm("mov.b64 %0, {%1, %2};" : "=l"(r) : "f"(lo), "f"(hi));
    return r;
}

// ---------------------------------------------------------------------------
// K2: transpose logits (i,b) -> g_logT (b,i)
// ---------------------------------------------------------------------------
__global__ __launch_bounds__(256) void k_transpose(const float* __restrict__ lg) {
    __shared__ float tile[32][33];
    const int i0 = blockIdx.x * 32, b0 = blockIdx.y * 32;
    const int tx = threadIdx.x & 31, ty = threadIdx.x >> 5;   // 32 x 8
#pragma unroll
    for (int j = 0; j < 4; ++j)
        tile[ty + 8 * j][tx] = lg[(size_t)(i0 + ty + 8 * j) * NBATCH + b0 + tx];
    __syncthreads();
#pragma unroll
    for (int j = 0; j < 4; ++j)
        g_logT[(size_t)(b0 + ty + 8 * j) * NINPUT + i0 + tx] = tile[tx][ty + 8 * j];
}

// ---------------------------------------------------------------------------
// K1: distances = maps @ ctx, threshold vs bias, pack 4 bits -> g_idx
// Grid 128 CTAs x 8 neurons (32 map rows). Threads: 4 s-groups x 64 b-quads.
// f32x2 packs over the batch dimension (map value duplicated in smem).
// ---------------------------------------------------------------------------
__global__ __launch_bounds__(256) void k_ctx_idx(
    const float* __restrict__ cmaps, const float* __restrict__ cbias,
    const float* __restrict__ ctx)
{
    __shared__ float2 msh[32 * 128];   // map values duplicated (v,v), per c-chunk
    __shared__ float cbsh[32];

    const int t  = threadIdx.x;
    const int s0 = blockIdx.x * SB;
    const int sg = t >> 6;             // 0..3 -> rows sg*8 .. sg*8+7 (2 neurons)
    const int bq = t & 63;
    const int b0 = bq * 4;

    if (t < 32) cbsh[t] = cbias[s0 * 4 + t];

    u64 acc[8][2];
#pragma unroll
    for (int r = 0; r < 8; ++r) { acc[r][0] = 0ull; acc[r][1] = 0ull; }

    const float* cmb = cmaps + (size_t)s0 * 4 * NCTX;

    for (int ch = 0; ch < 4; ++ch) {
        __syncthreads();
        // stage 32 rows x 128 c of maps, duplicated into float2
#pragma unroll
        for (int j = 0; j < 16; ++j) {
            int idx = t + j * 256;               // 0..4095
            int r = idx >> 7, cc = idx & 127;
            float v = cmb[r * NCTX + ch * 128 + cc];
            msh[r * 128 + cc] = make_float2(v, v);
        }
        __syncthreads();
        const float* cp = ctx + (size_t)(ch * 128) * NBATCH + b0;
#pragma unroll 4
        for (int cc = 0; cc < 128; ++cc) {
            float4 cv = *(const float4*)(cp + (size_t)cc * NBATCH);
            u64 c01 = pack2(cv.x, cv.y);
            u64 c23 = pack2(cv.z, cv.w);
#pragma unroll
            for (int r = 0; r < 8; ++r) {
                u64 m2 = *(const u64*)&msh[(sg * 8 + r) * 128 + cc];
                acc[r][0] = ffma2(m2, c01, acc[r][0]);
                acc[r][1] = ffma2(m2, c23, acc[r][1]);
            }
        }
    }

    // threshold + pack bits. rows r = local_neuron*4 + m
    unsigned pk[2] = {0u, 0u};
#pragma unroll
    for (int r = 0; r < 8; ++r) {
        float cb = cbsh[sg * 8 + r];
        float2 d01 = unpack2(acc[r][0]);
        float2 d23 = unpack2(acc[r][1]);
        int n = r >> 2;
        unsigned bit = 1u << (r & 3);
        unsigned add = 0;
        if (d01.x > cb) add |= bit;
        if (d01.y > cb) add |= bit << 8;
        if (d23.x > cb) add |= bit << 16;
        if (d23.y > cb) add |= bit << 24;
        pk[n] |= add;
    }
    const int sl = sg * 2;
    *(unsigned*)(g_idx + (size_t)(s0 + sl) * NBATCH + b0)     = pk[0];
    *(unsigned*)(g_idx + (size_t)(s0 + sl + 1) * NBATCH + b0) = pk[1];
}

// ---------------------------------------------------------------------------
// K3: per-CTA (8 neurons): winners, out = dot(w[s,idx[s,b]], logits[:,b]),
//     clip + bias override, sigmoid coef, weight update (clip +-5).
// f32x2 packs over adjacent i (weights contiguous in i; logT contiguous in i).
// ---------------------------------------------------------------------------
__global__ __launch_bounds__(256) void k_out_update(
    const float* __restrict__ targets,
    const float* __restrict__ W,
    const float* __restrict__ bias,
    float* __restrict__ out,
    float* __restrict__ Wout)
{
    __shared__ float2 ws2[32 * 129];        // [i-pair][row=(s*16+k)], padded
    __shared__ float  outv[SB * NBATCH];
    __shared__ int    win[SB * NBUCKET];
    __shared__ float  coef[SB * NBUCKET];

    const int t    = threadIdx.x;           // t == batch column b
    const int s0   = blockIdx.x * SB;
    const int wid  = t >> 5, lane = t & 31;

    int ks[SB];
#pragma unroll
    for (int si = 0; si < SB; ++si)
        ks[si] = g_idx[(size_t)(s0 + si) * NBATCH + t];

    if (t < SB * NBUCKET) win[t] = -1;
    __syncthreads();
#pragma unroll
    for (int si = 0; si < SB; ++si)
        atomicMax(&win[si * NBUCKET + ks[si]], t);   // last batch index wins

    u64 acc[SB];
#pragma unroll
    for (int si = 0; si < SB; ++si) acc[si] = 0ull;

    const u64* ltrow = (const u64*)(g_logT + (size_t)t * NINPUT);

    for (int ch = 0; ch < 16; ++ch) {
        __syncthreads();
        // stage 128 rows x 64 i of weights; warp wid stages rows wid*16..+15
#pragma unroll
        for (int q = 0; q < 16; ++q) {
            int rr = wid * 16 + q;
            float2 v = *(const float2*)(W + (size_t)(s0 * NBUCKET + rr) * NINPUT
                                          + ch * 64 + lane * 2);
            ws2[lane * 129 + rr] = v;
        }
        __syncthreads();
#pragma unroll 4
        for (int ip = 0; ip < 32; ++ip) {
            u64 l2 = ltrow[ch * 32 + ip];
#pragma unroll
            for (int si = 0; si < SB; ++si) {
                u64 w2 = *(const u64*)&ws2[ip * 129 + si * NBUCKET + ks[si]];
                acc[si] = ffma2(w2, l2, acc[si]);
            }
        }
    }

    const float LO = -4.59511985013459f, HI = 4.59511985013459f;
    const float bv = bias[0];
#pragma unroll
    for (int si = 0; si < SB; ++si) {
        float2 p = unpack2(acc[si]);
        float v = p.x + p.y;
        v = fminf(fmaxf(v, LO), HI);
        if (s0 + si == 0) v = bv;            // neuron 0 override (before sigmoid)
        outv[si * NBATCH + t] = v;
        out[(size_t)(s0 + si) * NBATCH + t] = v;
    }
    __syncthreads();

    if (t < SB * NBUCKET) {
        int bw = win[t];
        float cf = 0.0f;
        if (bw >= 0) {
            float o = outv[(t >> 4) * NBATCH + bw];
            float sg = 1.0f / (1.0f + expf(-o));
            cf = 0.01f * (sg - targets[bw]);
        }
        coef[t] = cf;
    }
    __syncthreads();

    // update pass: warp wid handles rows wid*16..+15
    for (int q = 0; q < 16; ++q) {
        int rr = wid * 16 + q;
        int bw = win[rr];
        float cf = coef[rr];
        const float4* wrow = (const float4*)(W    + (size_t)(s0 * NBUCKET + rr) * NINPUT);
        float4*       orow = (float4*)      (Wout + (size_t)(s0 * NBUCKET + rr) * NINPUT);
        if (bw >= 0) {
            const float4* lrow = (const float4*)(g_logT + (size_t)bw * NINPUT);
#pragma unroll
            for (int j = 0; j < 8; ++j) {
                float4 w4 = wrow[j * 32 + lane];
                float4 l4 = lrow[j * 32 + lane];
                float4 r4;
                r4.x = fminf(fmaxf(w4.x - cf * l4.x, -5.0f), 5.0f);
                r4.y = fminf(fmaxf(w4.y - cf * l4.y, -5.0f), 5.0f);
                r4.z = fminf(fmaxf(w4.z - cf * l4.z, -5.0f), 5.0f);
                r4.w = fminf(fmaxf(w4.w - cf * l4.w, -5.0f), 5.0f);
                orow[j * 32 + lane] = r4;
            }
        } else {
#pragma unroll
            for (int j = 0; j < 8; ++j)
                orow[j * 32 + lane] = wrow[j * 32 + lane];
        }
    }
}

// ---------------------------------------------------------------------------
extern "C" void kernel_launch(void* const* d_in, const int* in_sizes, int n_in,
                              void* d_out, int out_size) {
    const float* logits = (const float*)d_in[0];   // (1024, 256)
    const float* ctx    = (const float*)d_in[1];   // (512, 256)
    const float* tgt    = (const float*)d_in[2];   // (256,)
    const float* W      = (const float*)d_in[3];   // (1024, 16, 1024)
    const float* cmaps  = (const float*)d_in[4];   // (1024, 4, 512)
    const float* cbias  = (const float*)d_in[5];   // (1024, 4, 1)
    const float* bias   = (const float*)d_in[6];   // (1,)
    float* out  = (float*)d_out;                       // (1024, 256)
    float* Wout = out + (size_t)NSIZE * NBATCH;        // (1024, 16, 1024)

    k_transpose<<<dim3(32, 8), 256>>>(logits);
    k_ctx_idx<<<128, 256>>>(cmaps, cbias, ctx);
    k_out_update<<<128, 256>>>(tgt, W, bias, out, Wout);
}

// round 4
// speedup vs baseline: 1.9117x; 1.9117x over previous
#include <cuda_runtime.h>

#define NSIZE   1024
#define NINPUT  1024
#define NCTX    512
#define NBATCH  256
#define NBUCKET 16
#define SB      8          // neurons per CTA

static __device__ float g_logT[NBATCH * NINPUT];        // logits transposed: [b][i]
static __device__ unsigned char g_idx[NSIZE * NBATCH];  // bucket index per (s, b)

typedef unsigned long long u64;

__device__ __forceinline__ u64 ffma2(u64 a, u64 b, u64 c) {
    u64 d;
    asm("fma.rn.f32x2 %0, %1, %2, %3;" : "=l"(d) : "l"(a), "l"(b), "l"(c));
    return d;
}
__device__ __forceinline__ u64 fadd2(u64 a, u64 b) {
    u64 d;
    asm("add.rn.f32x2 %0, %1, %2;" : "=l"(d) : "l"(a), "l"(b));
    return d;
}
__device__ __forceinline__ float2 unpack2(u64 v) {
    float2 r;
    asm("mov.b64 {%0, %1}, %2;" : "=f"(r.x), "=f"(r.y) : "l"(v));
    return r;
}
__device__ __forceinline__ u64 pack2(float lo, float hi) {
    u64 r;
    asm("mov.b64 %0, {%1, %2};" : "=l"(r) : "f"(lo), "f"(hi));
    return r;
}
__device__ __forceinline__ void ldg2(u64& a, u64& b, const void* p) {
    asm("ld.global.nc.v2.b64 {%0, %1}, [%2];" : "=l"(a), "=l"(b) : "l"(p));
}
__device__ __forceinline__ float warp_sum(float v) {
#pragma unroll
    for (int off = 16; off; off >>= 1)
        v += __shfl_xor_sync(0xffffffffu, v, off);
    return v;
}
__device__ __forceinline__ float cl5(float x) { return fminf(fmaxf(x, -5.0f), 5.0f); }

// ---------------------------------------------------------------------------
// K2: transpose logits (i,b) -> g_logT (b,i)
// ---------------------------------------------------------------------------
__global__ __launch_bounds__(256) void k_transpose(const float* __restrict__ lg) {
    __shared__ float tile[32][33];
    const int i0 = blockIdx.x * 32, b0 = blockIdx.y * 32;
    const int tx = threadIdx.x & 31, ty = threadIdx.x >> 5;   // 32 x 8
#pragma unroll
    for (int j = 0; j < 4; ++j)
        tile[ty + 8 * j][tx] = lg[(size_t)(i0 + ty + 8 * j) * NBATCH + b0 + tx];
    __syncthreads();
#pragma unroll
    for (int j = 0; j < 4; ++j)
        g_logT[(size_t)(b0 + ty + 8 * j) * NINPUT + i0 + tx] = tile[tx][ty + 8 * j];
}

// ---------------------------------------------------------------------------
// K1: distances = maps @ ctx, threshold vs bias, pack 4 bits -> g_idx
// ---------------------------------------------------------------------------
__global__ __launch_bounds__(256) void k_ctx_idx(
    const float* __restrict__ cmaps, const float* __restrict__ cbias,
    const float* __restrict__ ctx)
{
    __shared__ float2 msh[32 * 128];
    __shared__ float cbsh[32];

    const int t  = threadIdx.x;
    const int s0 = blockIdx.x * SB;
    const int sg = t >> 6;
    const int bq = t & 63;
    const int b0 = bq * 4;

    if (t < 32) cbsh[t] = cbias[s0 * 4 + t];

    u64 acc[8][2];
#pragma unroll
    for (int r = 0; r < 8; ++r) { acc[r][0] = 0ull; acc[r][1] = 0ull; }

    const float* cmb = cmaps + (size_t)s0 * 4 * NCTX;

    for (int ch = 0; ch < 4; ++ch) {
        __syncthreads();
#pragma unroll
        for (int j = 0; j < 16; ++j) {
            int idx = t + j * 256;
            int r = idx >> 7, cc = idx & 127;
            float v = cmb[r * NCTX + ch * 128 + cc];
            msh[r * 128 + cc] = make_float2(v, v);
        }
        __syncthreads();
        const float* cp = ctx + (size_t)(ch * 128) * NBATCH + b0;
#pragma unroll 4
        for (int cc = 0; cc < 128; ++cc) {
            float4 cv = *(const float4*)(cp + (size_t)cc * NBATCH);
            u64 c01 = pack2(cv.x, cv.y);
            u64 c23 = pack2(cv.z, cv.w);
#pragma unroll
            for (int r = 0; r < 8; ++r) {
                u64 m2 = *(const u64*)&msh[(sg * 8 + r) * 128 + cc];
                acc[r][0] = ffma2(m2, c01, acc[r][0]);
                acc[r][1] = ffma2(m2, c23, acc[r][1]);
            }
        }
    }

    unsigned pk[2] = {0u, 0u};
#pragma unroll
    for (int r = 0; r < 8; ++r) {
        float cb = cbsh[sg * 8 + r];
        float2 d01 = unpack2(acc[r][0]);
        float2 d23 = unpack2(acc[r][1]);
        int n = r >> 2;
        unsigned bit = 1u << (r & 3);
        unsigned add = 0;
        if (d01.x > cb) add |= bit;
        if (d01.y > cb) add |= bit << 8;
        if (d23.x > cb) add |= bit << 16;
        if (d23.y > cb) add |= bit << 24;
        pk[n] |= add;
    }
    const int sl = sg * 2;
    *(unsigned*)(g_idx + (size_t)(s0 + sl) * NBATCH + b0)     = pk[0];
    *(unsigned*)(g_idx + (size_t)(s0 + sl + 1) * NBATCH + b0) = pk[1];
}

// ---------------------------------------------------------------------------
// K3 fused: warp-per-neuron. Bucket-group the batch, keep W row in registers,
// dot 2 batch-columns per iteration, update row in-register, write once.
// ---------------------------------------------------------------------------
__global__ __launch_bounds__(256) void k_fused(
    const float* __restrict__ tgt,
    const float* __restrict__ W,
    const float* __restrict__ bias,
    float* __restrict__ out,
    float* __restrict__ Wout)
{
    __shared__ unsigned       msk[SB][128];         // [warp][k*8 + word]
    __shared__ unsigned char  ord[SB][NBATCH];      // b's grouped by bucket, ascending
    __shared__ unsigned short offs[SB][NBUCKET + 1];

    const int w = threadIdx.x >> 5, lane = threadIdx.x & 31;
    const int s = blockIdx.x * SB + w;

    unsigned* M = msk[w];
    M[lane] = 0; M[lane + 32] = 0; M[lane + 64] = 0; M[lane + 96] = 0;
    __syncwarp();

    // scatter batch indices into per-bucket bitmasks
    {
        u64 ib = *(const u64*)(g_idx + (size_t)s * NBATCH + lane * 8);
#pragma unroll
        for (int e = 0; e < 8; ++e) {
            int b = lane * 8 + e;
            int k = (int)((ib >> (8 * e)) & 0xF);
            atomicOr(&M[k * 8 + (b >> 5)], 1u << (b & 31));
        }
    }
    __syncwarp();

    // counts -> exclusive offsets (scan over first 16 lanes)
    {
        int cnt = 0;
        if (lane < NBUCKET) {
#pragma unroll
            for (int wd = 0; wd < 8; ++wd) cnt += __popc(M[lane * 8 + wd]);
        }
        int sc = cnt;
#pragma unroll
        for (int d = 1; d < 16; d <<= 1) {
            int o = __shfl_up_sync(0xffffffffu, sc, d);
            if (lane >= d) sc += o;
        }
        if (lane == 0) offs[w][0] = 0;
        if (lane < NBUCKET) offs[w][lane + 1] = (unsigned short)sc;
    }
    __syncwarp();

    // fill ordered list (lane k walks its bucket's mask, ascending b)
    if (lane < NBUCKET) {
        int p = offs[w][lane];
#pragma unroll
        for (int wd = 0; wd < 8; ++wd) {
            unsigned m = M[lane * 8 + wd];
            while (m) {
                int b = wd * 32 + __ffs(m) - 1;
                ord[w][p++] = (unsigned char)b;
                m &= m - 1;
            }
        }
    }
    __syncwarp();

    const float LO = -4.59511985013459f, HI = 4.59511985013459f;
    const float bv = bias[0];

    for (int k = 0; k < NBUCKET; ++k) {
        const int o0 = offs[w][k];
        const int n  = offs[w][k + 1] - o0;

        // W row -> registers (coalesced: lane*16B, stride 512B)
        u64 wa[16];
        const char* wb = (const char*)(W + ((size_t)s * NBUCKET + k) * NINPUT) + lane * 16;
#pragma unroll
        for (int j = 0; j < 8; ++j) ldg2(wa[2 * j], wa[2 * j + 1], wb + j * 512);

        float vlast = 0.0f;
        for (int jj = 0; jj < n; jj += 2) {
            const int  b0  = ord[w][o0 + jj];
            const bool two = (jj + 1 < n);
            const int  b1  = two ? ord[w][o0 + jj + 1] : b0;

            const char* l0 = (const char*)(g_logT + (size_t)b0 * NINPUT) + lane * 16;
            const char* l1 = (const char*)(g_logT + (size_t)b1 * NINPUT) + lane * 16;

            u64 a0 = 0, a1 = 0, a2 = 0, a3 = 0;
            u64 c0 = 0, c1 = 0, c2 = 0, c3 = 0;
#pragma unroll
            for (int j = 0; j < 8; ++j) {
                u64 x, y;
                ldg2(x, y, l0 + j * 512);
                if (j & 1) { a2 = ffma2(wa[2 * j], x, a2); a3 = ffma2(wa[2 * j + 1], y, a3); }
                else       { a0 = ffma2(wa[2 * j], x, a0); a1 = ffma2(wa[2 * j + 1], y, a1); }
                u64 p, q;
                ldg2(p, q, l1 + j * 512);
                if (j & 1) { c2 = ffma2(wa[2 * j], p, c2); c3 = ffma2(wa[2 * j + 1], q, c3); }
                else       { c0 = ffma2(wa[2 * j], p, c0); c1 = ffma2(wa[2 * j + 1], q, c1); }
            }
            float2 pa = unpack2(fadd2(fadd2(a0, a1), fadd2(a2, a3)));
            float2 pc = unpack2(fadd2(fadd2(c0, c1), fadd2(c2, c3)));
            float v0 = warp_sum(pa.x + pa.y);
            float v1 = warp_sum(pc.x + pc.y);

            v0 = fminf(fmaxf(v0, LO), HI);
            v1 = fminf(fmaxf(v1, LO), HI);
            if (s == 0) { v0 = bv; v1 = bv; }
            if (lane == 0) {
                out[(size_t)s * NBATCH + b0] = v0;
                if (two) out[(size_t)s * NBATCH + b1] = v1;
            }
            vlast = two ? v1 : v0;
        }

        // update (winner = last/highest b in the bucket) or passthrough
        char* wob = (char*)(Wout + ((size_t)s * NBUCKET + k) * NINPUT) + lane * 16;
        if (n > 0) {
            const int bwin = ord[w][o0 + n - 1];
            float o  = vlast;
            float cf = 0.01f * (1.0f / (1.0f + expf(-o)) - tgt[bwin]);
            u64 nc2 = pack2(-cf, -cf);
            const char* lw = (const char*)(g_logT + (size_t)bwin * NINPUT) + lane * 16;
#pragma unroll
            for (int j = 0; j < 8; ++j) {
                u64 x, y;
                ldg2(x, y, lw + j * 512);
                float2 r0 = unpack2(ffma2(x, nc2, wa[2 * j]));
                float2 r1 = unpack2(ffma2(y, nc2, wa[2 * j + 1]));
                float4 f4;
                f4.x = cl5(r0.x); f4.y = cl5(r0.y);
                f4.z = cl5(r1.x); f4.w = cl5(r1.y);
                *(float4*)(wob + j * 512) = f4;
            }
        } else {
#pragma unroll
            for (int j = 0; j < 8; ++j) {
                float2 r0 = unpack2(wa[2 * j]);
                float2 r1 = unpack2(wa[2 * j + 1]);
                float4 f4; f4.x = r0.x; f4.y = r0.y; f4.z = r1.x; f4.w = r1.y;
                *(float4*)(wob + j * 512) = f4;
            }
        }
    }
}

// ---------------------------------------------------------------------------
extern "C" void kernel_launch(void* const* d_in, const int* in_sizes, int n_in,
                              void* d_out, int out_size) {
    const float* logits = (const float*)d_in[0];   // (1024, 256)
    const float* ctx    = (const float*)d_in[1];   // (512, 256)
    const float* tgt    = (const float*)d_in[2];   // (256,)
    const float* W      = (const float*)d_in[3];   // (1024, 16, 1024)
    const float* cmaps  = (const float*)d_in[4];   // (1024, 4, 512)
    const float* cbias  = (const float*)d_in[5];   // (1024, 4, 1)
    const float* bias   = (const float*)d_in[6];   // (1,)
    float* out  = (float*)d_out;                       // (1024, 256)
    float* Wout = out + (size_t)NSIZE * NBATCH;        // (1024, 16, 1024)

    k_transpose<<<dim3(32, 8), 256>>>(logits);
    k_ctx_idx<<<128, 256>>>(cmaps, cbias, ctx);
    k_fused<<<128, 256>>>(tgt, W, bias, out, Wout);
}

// round 5
// speedup vs baseline: 2.2880x; 1.1968x over previous
#include <cuda_runtime.h>

#define NSIZE   1024
#define NINPUT  1024
#define NCTX    512
#define NBATCH  256
#define NBUCKET 16
#define SB      8

static __device__ float g_logT[NBATCH * NINPUT];        // logits transposed: [b][i]
static __device__ unsigned char g_idx[NSIZE * NBATCH];  // bucket index per (s, b)
static __device__ float g_coef[NSIZE * NBUCKET];        // per-row update coef
static __device__ int   g_win [NSIZE * NBUCKET];        // per-row winner b (-1 = none)

typedef unsigned long long u64;

__device__ __forceinline__ u64 ffma2(u64 a, u64 b, u64 c) {
    u64 d;
    asm("fma.rn.f32x2 %0, %1, %2, %3;" : "=l"(d) : "l"(a), "l"(b), "l"(c));
    return d;
}
__device__ __forceinline__ u64 fadd2(u64 a, u64 b) {
    u64 d;
    asm("add.rn.f32x2 %0, %1, %2;" : "=l"(d) : "l"(a), "l"(b));
    return d;
}
__device__ __forceinline__ float2 unpack2(u64 v) {
    float2 r;
    asm("mov.b64 {%0, %1}, %2;" : "=f"(r.x), "=f"(r.y) : "l"(v));
    return r;
}
__device__ __forceinline__ u64 pack2(float lo, float hi) {
    u64 r;
    asm("mov.b64 %0, {%1, %2};" : "=l"(r) : "f"(lo), "f"(hi));
    return r;
}
__device__ __forceinline__ void ldg2(u64& a, u64& b, const void* p) {
    asm("ld.global.nc.v2.b64 {%0, %1}, [%2];" : "=l"(a), "=l"(b) : "l"(p));
}
__device__ __forceinline__ float warp_sum(float v) {
#pragma unroll
    for (int off = 16; off; off >>= 1)
        v += __shfl_xor_sync(0xffffffffu, v, off);
    return v;
}
__device__ __forceinline__ float cl5(float x) { return fminf(fmaxf(x, -5.0f), 5.0f); }

// ---------------------------------------------------------------------------
// K1: distances = maps @ ctx, threshold vs bias, pack 4 bits -> g_idx
// (launched FIRST so ncu's captured launch profiles it)
// ---------------------------------------------------------------------------
__global__ __launch_bounds__(256) void k_ctx_idx(
    const float* __restrict__ cmaps, const float* __restrict__ cbias,
    const float* __restrict__ ctx)
{
    __shared__ float2 msh[32 * 128];
    __shared__ float cbsh[32];

    const int t  = threadIdx.x;
    const int s0 = blockIdx.x * SB;
    const int sg = t >> 6;
    const int bq = t & 63;
    const int b0 = bq * 4;

    if (t < 32) cbsh[t] = cbias[s0 * 4 + t];

    u64 acc[8][2];
#pragma unroll
    for (int r = 0; r < 8; ++r) { acc[r][0] = 0ull; acc[r][1] = 0ull; }

    const float* cmb = cmaps + (size_t)s0 * 4 * NCTX;

    for (int ch = 0; ch < 4; ++ch) {
        __syncthreads();
#pragma unroll
        for (int j = 0; j < 16; ++j) {
            int idx = t + j * 256;
            int r = idx >> 7, cc = idx & 127;
            float v = cmb[r * NCTX + ch * 128 + cc];
            msh[r * 128 + cc] = make_float2(v, v);
        }
        __syncthreads();
        const float* cp = ctx + (size_t)(ch * 128) * NBATCH + b0;
#pragma unroll 4
        for (int cc = 0; cc < 128; ++cc) {
            float4 cv = *(const float4*)(cp + (size_t)cc * NBATCH);
            u64 c01 = pack2(cv.x, cv.y);
            u64 c23 = pack2(cv.z, cv.w);
#pragma unroll
            for (int r = 0; r < 8; ++r) {
                u64 m2 = *(const u64*)&msh[(sg * 8 + r) * 128 + cc];
                acc[r][0] = ffma2(m2, c01, acc[r][0]);
                acc[r][1] = ffma2(m2, c23, acc[r][1]);
            }
        }
    }

    unsigned pk[2] = {0u, 0u};
#pragma unroll
    for (int r = 0; r < 8; ++r) {
        float cb = cbsh[sg * 8 + r];
        float2 d01 = unpack2(acc[r][0]);
        float2 d23 = unpack2(acc[r][1]);
        int n = r >> 2;
        unsigned bit = 1u << (r & 3);
        unsigned add = 0;
        if (d01.x > cb) add |= bit;
        if (d01.y > cb) add |= bit << 8;
        if (d23.x > cb) add |= bit << 16;
        if (d23.y > cb) add |= bit << 24;
        pk[n] |= add;
    }
    const int sl = sg * 2;
    *(unsigned*)(g_idx + (size_t)(s0 + sl) * NBATCH + b0)     = pk[0];
    *(unsigned*)(g_idx + (size_t)(s0 + sl + 1) * NBATCH + b0) = pk[1];
}

// ---------------------------------------------------------------------------
// K2: transpose logits (i,b) -> g_logT (b,i)
// ---------------------------------------------------------------------------
__global__ __launch_bounds__(256) void k_transpose(const float* __restrict__ lg) {
    __shared__ float tile[32][33];
    const int i0 = blockIdx.x * 32, b0 = blockIdx.y * 32;
    const int tx = threadIdx.x & 31, ty = threadIdx.x >> 5;
#pragma unroll
    for (int j = 0; j < 4; ++j)
        tile[ty + 8 * j][tx] = lg[(size_t)(i0 + ty + 8 * j) * NBATCH + b0 + tx];
    __syncthreads();
#pragma unroll
    for (int j = 0; j < 4; ++j)
        g_logT[(size_t)(b0 + ty + 8 * j) * NINPUT + i0 + tx] = tile[tx][ty + 8 * j];
}

// ---------------------------------------------------------------------------
// K3: dots. 2 warps per neuron (8 buckets each), 4 warps/CTA, grid 512.
// Bucket-group batch columns, keep W row in regs, 2 columns per iteration.
// Emits out[s,b], g_win[row], g_coef[row].
// ---------------------------------------------------------------------------
__global__ __launch_bounds__(128, 4) void k_dots(
    const float* __restrict__ tgt,
    const float* __restrict__ W,
    const float* __restrict__ bias,
    float* __restrict__ out)
{
    __shared__ unsigned       msk[4][64];        // [warp][kk*8 + word]
    __shared__ unsigned char  ord[4][NBATCH];
    __shared__ unsigned short offs[4][9];

    const int w = threadIdx.x >> 5, lane = threadIdx.x & 31;
    const int sid  = blockIdx.x * 4 + w;
    const int s    = sid >> 1;
    const int half = sid & 1;           // buckets half*8 .. half*8+7

    unsigned* M = msk[w];
    M[lane] = 0; M[lane + 32] = 0;
    __syncwarp();

    {
        u64 ib = *(const u64*)(g_idx + (size_t)s * NBATCH + lane * 8);
#pragma unroll
        for (int e = 0; e < 8; ++e) {
            int b = lane * 8 + e;
            int k = (int)((ib >> (8 * e)) & 0xF);
            if ((k >> 3) == half)
                atomicOr(&M[(k & 7) * 8 + (b >> 5)], 1u << (b & 31));
        }
    }
    __syncwarp();

    {
        int cnt = 0;
        if (lane < 8) {
#pragma unroll
            for (int wd = 0; wd < 8; ++wd) cnt += __popc(M[lane * 8 + wd]);
        }
        int sc = cnt;
#pragma unroll
        for (int d = 1; d < 8; d <<= 1) {
            int o = __shfl_up_sync(0xffffffffu, sc, d);
            if (lane >= d) sc += o;
        }
        if (lane == 0) offs[w][0] = 0;
        if (lane < 8) offs[w][lane + 1] = (unsigned short)sc;
    }
    __syncwarp();

    if (lane < 8) {
        int p = offs[w][lane];
#pragma unroll
        for (int wd = 0; wd < 8; ++wd) {
            unsigned m = M[lane * 8 + wd];
            while (m) {
                int b = wd * 32 + __ffs(m) - 1;
                ord[w][p++] = (unsigned char)b;
                m &= m - 1;
            }
        }
    }
    __syncwarp();

    const float LO = -4.59511985013459f, HI = 4.59511985013459f;
    const float bv = bias[0];

    for (int kk = 0; kk < 8; ++kk) {
        const int o0 = offs[w][kk];
        const int n  = offs[w][kk + 1] - o0;
        const int row = s * NBUCKET + half * 8 + kk;

        if (n == 0) {
            if (lane == 0) { g_win[row] = -1; g_coef[row] = 0.0f; }
            continue;
        }

        u64 wa[16];
        const char* wb = (const char*)(W + (size_t)row * NINPUT) + lane * 16;
#pragma unroll
        for (int j = 0; j < 8; ++j) ldg2(wa[2 * j], wa[2 * j + 1], wb + j * 512);

        float vlast = 0.0f;
        for (int jj = 0; jj < n; jj += 2) {
            const int  b0  = ord[w][o0 + jj];
            const bool two = (jj + 1 < n);
            const int  b1  = two ? ord[w][o0 + jj + 1] : b0;

            const char* l0 = (const char*)(g_logT + (size_t)b0 * NINPUT) + lane * 16;
            const char* l1 = (const char*)(g_logT + (size_t)b1 * NINPUT) + lane * 16;

            u64 a0 = 0, a1 = 0, a2 = 0, a3 = 0;
            u64 c0 = 0, c1 = 0, c2 = 0, c3 = 0;
#pragma unroll
            for (int j = 0; j < 8; ++j) {
                u64 x, y;
                ldg2(x, y, l0 + j * 512);
                if (j & 1) { a2 = ffma2(wa[2 * j], x, a2); a3 = ffma2(wa[2 * j + 1], y, a3); }
                else       { a0 = ffma2(wa[2 * j], x, a0); a1 = ffma2(wa[2 * j + 1], y, a1); }
                u64 p, q;
                ldg2(p, q, l1 + j * 512);
                if (j & 1) { c2 = ffma2(wa[2 * j], p, c2); c3 = ffma2(wa[2 * j + 1], q, c3); }
                else       { c0 = ffma2(wa[2 * j], p, c0); c1 = ffma2(wa[2 * j + 1], q, c1); }
            }
            float2 pa = unpack2(fadd2(fadd2(a0, a1), fadd2(a2, a3)));
            float2 pc = unpack2(fadd2(fadd2(c0, c1), fadd2(c2, c3)));
            float v0 = warp_sum(pa.x + pa.y);
            float v1 = warp_sum(pc.x + pc.y);

            v0 = fminf(fmaxf(v0, LO), HI);
            v1 = fminf(fmaxf(v1, LO), HI);
            if (s == 0) { v0 = bv; v1 = bv; }
            if (lane == 0) {
                out[(size_t)s * NBATCH + b0] = v0;
                if (two) out[(size_t)s * NBATCH + b1] = v1;
            }
            vlast = two ? v1 : v0;
        }

        if (lane == 0) {
            const int bwin = ord[w][o0 + n - 1];   // highest b = last update wins
            float cf = 0.01f * (1.0f / (1.0f + expf(-vlast)) - tgt[bwin]);
            g_win[row]  = bwin;
            g_coef[row] = cf;
        }
    }
}

// ---------------------------------------------------------------------------
// K4: streaming weight update. Warp per row, 8 rows per CTA, grid 2048.
// ---------------------------------------------------------------------------
__global__ __launch_bounds__(256) void k_update(
    const float* __restrict__ W,
    float* __restrict__ Wout)
{
    const int wid = threadIdx.x >> 5, lane = threadIdx.x & 31;
    const int row = blockIdx.x * 8 + wid;

    const int   bw = g_win[row];
    const float cf = g_coef[row];

    const char* wb  = (const char*)(W    + (size_t)row * NINPUT) + lane * 16;
    char*       wob = (char*)      (Wout + (size_t)row * NINPUT) + lane * 16;

    if (bw >= 0) {
        u64 nc2 = pack2(-cf, -cf);
        const char* lw = (const char*)(g_logT + (size_t)bw * NINPUT) + lane * 16;
#pragma unroll
        for (int j = 0; j < 8; ++j) {
            u64 a, b, x, y;
            ldg2(a, b, wb + j * 512);
            ldg2(x, y, lw + j * 512);
            float2 r0 = unpack2(ffma2(x, nc2, a));
            float2 r1 = unpack2(ffma2(y, nc2, b));
            float4 f4;
            f4.x = cl5(r0.x); f4.y = cl5(r0.y);
            f4.z = cl5(r1.x); f4.w = cl5(r1.y);
            *(float4*)(wob + j * 512) = f4;
        }
    } else {
#pragma unroll
        for (int j = 0; j < 8; ++j) {
            u64 a, b;
            ldg2(a, b, wb + j * 512);
            float2 r0 = unpack2(a);
            float2 r1 = unpack2(b);
            float4 f4; f4.x = r0.x; f4.y = r0.y; f4.z = r1.x; f4.w = r1.y;
            *(float4*)(wob + j * 512) = f4;
        }
    }
}

// ---------------------------------------------------------------------------
extern "C" void kernel_launch(void* const* d_in, const int* in_sizes, int n_in,
                              void* d_out, int out_size) {
    const float* logits = (const float*)d_in[0];   // (1024, 256)
    const float* ctx    = (const float*)d_in[1];   // (512, 256)
    const float* tgt    = (const float*)d_in[2];   // (256,)
    const float* W      = (const float*)d_in[3];   // (1024, 16, 1024)
    const float* cmaps  = (const float*)d_in[4];   // (1024, 4, 512)
    const float* cbias  = (const float*)d_in[5];   // (1024, 4, 1)
    const float* bias   = (const float*)d_in[6];   // (1,)
    float* out  = (float*)d_out;                       // (1024, 256)
    float* Wout = out + (size_t)NSIZE * NBATCH;        // (1024, 16, 1024)

    k_ctx_idx<<<128, 256>>>(cmaps, cbias, ctx);
    k_transpose<<<dim3(32, 8), 256>>>(logits);
    k_dots<<<512, 128>>>(tgt, W, bias, out);
    k_update<<<2048, 256>>>(W, Wout);
}